// round 17
// baseline (speedup 1.0000x reference)
#include <cuda_runtime.h>
#include <cooperative_groups.h>

namespace cg = cooperative_groups;

#define B 64
#define N 16384
#define M 64
#define FULLM 0xFFFFFFFFu

// scratch (device globals — no allocation allowed)
__device__ float g_s[B * N];        // exp(beta*cos) from k1
__device__ float g_part[B * 256];   // per-block partial sums (k1 grid.x = 256)

// ---------------------------------------------------------------------------
// k1 (proven ~41.7us, unchanged): exp(beta*cos) per row + deterministic
// per-block partial sum. 8 lanes/row, 2 rows/thread -> 4 LDG.128.CS in
// flight; ~55 regs. Block = 256 thr -> 64 rows. Grid (256, B).
// ---------------------------------------------------------------------------
__global__ __launch_bounds__(256) void k1_logits(
    const float* __restrict__ key,    // [B, M]
    const float* __restrict__ beta,   // [B, 1]
    const float* __restrict__ mem)    // [B, N, M]
{
    const int b    = blockIdx.y;
    const int tid  = threadIdx.x;
    const int l    = tid & 7;
    const int grp  = tid >> 3;
    const int row0 = blockIdx.x * 64;

    const float4* kp = reinterpret_cast<const float4*>(key + b * M);
    const float4 ka = kp[l];
    const float4 kb = kp[l + 8];
    float ks = ka.x * ka.x + ka.y * ka.y + ka.z * ka.z + ka.w * ka.w
             + kb.x * kb.x + kb.y * kb.y + kb.z * kb.z + kb.w * kb.w;

    float4 ma[2], mb[2];
#pragma unroll
    for (int u = 0; u < 2; ++u) {
        const int row = row0 + u * 32 + grp;
        const float4* mp = reinterpret_cast<const float4*>(
            mem + ((size_t)b * N + row) * M);
        ma[u] = __ldcs(mp + l);
        mb[u] = __ldcs(mp + l + 8);
    }

    float dt[2], ms[2];
#pragma unroll
    for (int u = 0; u < 2; ++u) {
        dt[u] = ka.x * ma[u].x + ka.y * ma[u].y + ka.z * ma[u].z + ka.w * ma[u].w
              + kb.x * mb[u].x + kb.y * mb[u].y + kb.z * mb[u].z + kb.w * mb[u].w;
        ms[u] = ma[u].x * ma[u].x + ma[u].y * ma[u].y + ma[u].z * ma[u].z + ma[u].w * ma[u].w
              + mb[u].x * mb[u].x + mb[u].y * mb[u].y + mb[u].z * mb[u].z + mb[u].w * mb[u].w;
    }

#pragma unroll
    for (int off = 1; off <= 4; off <<= 1) {
        ks    += __shfl_xor_sync(FULLM, ks,    off);
        dt[0] += __shfl_xor_sync(FULLM, dt[0], off);
        dt[1] += __shfl_xor_sync(FULLM, dt[1], off);
        ms[0] += __shfl_xor_sync(FULLM, ms[0], off);
        ms[1] += __shfl_xor_sync(FULLM, ms[1], off);
    }

    float esum = 0.0f;
    if (l == 0) {
        const float kn = sqrtf(ks);
        const float be = __ldg(beta + b);
#pragma unroll
        for (int u = 0; u < 2; ++u) {
            const int row = row0 + u * 32 + grp;
            const float denom = fmaxf(kn * sqrtf(ms[u]), 1e-8f);
            const float e = __expf(be * (dt[u] / denom));
            g_s[b * N + row] = e;
            esum += e;
        }
    }

    __shared__ float sred[8];
#pragma unroll
    for (int o = 16; o > 0; o >>= 1)
        esum += __shfl_xor_sync(FULLM, esum, o);
    if ((tid & 31) == 0) sred[tid >> 5] = esum;
    __syncthreads();
    if (tid == 0) {
        float s = 0.0f;
#pragma unroll
        for (int w = 0; w < 8; ++w) s += sred[w];
        g_part[b * 256 + blockIdx.x] = s;
    }
}

// ---------------------------------------------------------------------------
// k2: R14 structure, re-dimensioned to cluster-8 / 512 CTAs x 128 thr so PDL
// secondary CTAs fit into k1's drain holes earlier. CTA q of batch b owns
// elems [q*2048, (q+1)*2048); 4 float4 per thread per array. Preamble: last
// vectors + CTA-edge last. Post-sync: 4 vector g_s loads, warp0 S-reduce,
// gated interp, edge publish, conv+pow, psum reduce, cluster-8 DSMEM combine
// in fixed rank order (deterministic), store.
// ---------------------------------------------------------------------------
__global__ __launch_bounds__(128) __cluster_dims__(8, 1, 1)
void k2_address(
    const float* __restrict__ gate,     // [B,1]
    const float* __restrict__ shift,    // [B,3]
    const float* __restrict__ sharpen,  // [B,1]
    const float* __restrict__ last,     // [B,N]
    float* __restrict__ out)            // [B,N]
{
    cg::cluster_group cluster = cg::this_cluster();

    const int cta  = blockIdx.x;     // 0..511
    const int b    = cta >> 3;
    const int q    = cta & 7;        // eighth of the batch (== cluster rank)
    const int tid  = threadIdx.x;
    const int warp = tid >> 5;       // 0..3
    const int lane = tid & 31;

    __shared__ float sred[4];
    __shared__ float sS;
    __shared__ float edgeL[16];      // [warp*4+k] : lane0's  w4[k].x
    __shared__ float edgeR[16];      // [warp*4+k] : lane31's w4[k].w
    __shared__ float sCtaL, sCtaR;
    __shared__ float cpsum;          // DSMEM target

    // ======= PDL preamble: everything independent of k1's output =======
    const int base4 = (b << 12) + (q << 9);  // float4 index of this CTA's span
    const float4* lp4 = reinterpret_cast<const float4*>(last);

    float4 a4[4];
#pragma unroll
    for (int k = 0; k < 4; ++k)
        a4[k] = lp4[base4 + k * 128 + tid];

    // CTA-circular edge indices + last[] values (2 threads)
    int   edgeIdx = -1;
    float edgeLast = 0.0f;
    if (tid == 0)   edgeIdx = b * N + (((q << 11) + N - 1) & (N - 1));
    if (tid == 127) edgeIdx = b * N + (((q << 11) + 2048) & (N - 1));
    if (edgeIdx >= 0) edgeLast = last[edgeIdx];

    const float g  = __ldg(gate + b);
    const float og = 1.0f - g;
    const float s0 = __ldg(shift + b * 3 + 0);
    const float s1 = __ldg(shift + b * 3 + 1);
    const float s2 = __ldg(shift + b * 3 + 2);
    const float sh = __ldg(sharpen + b);

    // ======= wait for k1 grid completion (memory-visible) =======
    cudaGridDependencySynchronize();

    // post-sync loads first (front-batched)
    const float4* sp4 = reinterpret_cast<const float4*>(g_s);
    float4 e4[4];
#pragma unroll
    for (int k = 0; k < 4; ++k)
        e4[k] = sp4[base4 + k * 128 + tid];

    float edgeS = 0.0f;
    if (edgeIdx >= 0) edgeS = g_s[edgeIdx];

    // softmax denominator from k1 partials (warp 0)
    if (warp == 0) {
        const float* pp = g_part + b * 256;
        float S = 0.0f;
#pragma unroll
        for (int j = 0; j < 8; ++j) S += pp[j * 32 + lane];
#pragma unroll
        for (int o = 16; o > 0; o >>= 1)
            S += __shfl_xor_sync(FULLM, S, o);
        if (lane == 0) sS = S;
    }
    __syncthreads();

    const float gS = g / sS;

    // ---- gate interpolation in registers; publish gated edges ----
    float4 w4[4];
#pragma unroll
    for (int k = 0; k < 4; ++k) {
        w4[k].x = fmaf(gS, e4[k].x, og * a4[k].x);
        w4[k].y = fmaf(gS, e4[k].y, og * a4[k].y);
        w4[k].z = fmaf(gS, e4[k].z, og * a4[k].z);
        w4[k].w = fmaf(gS, e4[k].w, og * a4[k].w);
    }
    if (lane == 0) {
#pragma unroll
        for (int k = 0; k < 4; ++k) edgeL[warp * 4 + k] = w4[k].x;
    }
    if (lane == 31) {
#pragma unroll
        for (int k = 0; k < 4; ++k) edgeR[warp * 4 + k] = w4[k].w;
    }
    if (tid == 0)   sCtaL = fmaf(gS, edgeS, og * edgeLast);
    if (tid == 127) sCtaR = fmaf(gS, edgeS, og * edgeLast);
    __syncthreads();

    // ---- circular 3-tap conv + sharpen; halos via shuffles + edge table ----
    float4 p4[4];
    float psum = 0.0f;
#pragma unroll
    for (int k = 0; k < 4; ++k) {
        float left = __shfl_up_sync(FULLM, w4[k].w, 1);
        if (lane == 0)
            left = (warp > 0) ? edgeR[(warp - 1) * 4 + k]
                 : (k > 0)    ? edgeR[3 * 4 + (k - 1)]
                              : sCtaL;
        float right = __shfl_down_sync(FULLM, w4[k].x, 1);
        if (lane == 31)
            right = (warp < 3) ? edgeL[(warp + 1) * 4 + k]
                  : (k < 3)    ? edgeL[k + 1]
                               : sCtaR;

        p4[k].x = __powf(s0 * left    + s1 * w4[k].x + s2 * w4[k].y, sh);
        p4[k].y = __powf(s0 * w4[k].x + s1 * w4[k].y + s2 * w4[k].z, sh);
        p4[k].z = __powf(s0 * w4[k].y + s1 * w4[k].z + s2 * w4[k].w, sh);
        p4[k].w = __powf(s0 * w4[k].z + s1 * w4[k].w + s2 * right,  sh);
        psum += p4[k].x + p4[k].y + p4[k].z + p4[k].w;
    }

    // ---- CTA psum reduce (deterministic) ----
#pragma unroll
    for (int o = 16; o > 0; o >>= 1)
        psum += __shfl_xor_sync(FULLM, psum, o);
    if (lane == 0) sred[warp] = psum;
    __syncthreads();
    if (tid == 0) {
        float x = 0.0f;
#pragma unroll
        for (int w = 0; w < 4; ++w) x += sred[w];
        cpsum = x;
    }

    // ---- cluster-8 combine via DSMEM (fixed rank order -> deterministic) ----
    cluster.sync();
    float P = 0.0f;
#pragma unroll
    for (int r = 0; r < 8; ++r)
        P += *cluster.map_shared_rank(&cpsum, r);
    cluster.sync();  // keep peer smem alive until everyone has read

    const float invP = 1.0f / (P + 1e-16f);

    float4* op4 = reinterpret_cast<float4*>(out);
#pragma unroll
    for (int k = 0; k < 4; ++k) {
        float4 p = p4[k];
        p.x *= invP; p.y *= invP; p.z *= invP; p.w *= invP;
        op4[base4 + k * 128 + tid] = p;
    }
}

extern "C" void kernel_launch(void* const* d_in, const int* in_sizes, int n_in,
                              void* d_out, int out_size) {
    const float* key     = (const float*)d_in[0];
    const float* beta    = (const float*)d_in[1];
    const float* gate    = (const float*)d_in[2];
    const float* shift   = (const float*)d_in[3];
    const float* sharpen = (const float*)d_in[4];
    const float* last    = (const float*)d_in[5];
    const float* mem     = (const float*)d_in[6];
    float* out = (float*)d_out;

    dim3 g1(N / 64, B);
    k1_logits<<<g1, 256>>>(key, beta, mem);

    cudaLaunchConfig_t cfg = {};
    cfg.gridDim  = dim3(B * 8);
    cfg.blockDim = dim3(128);
    cudaLaunchAttribute attrs[1];
    attrs[0].id = cudaLaunchAttributeProgrammaticStreamSerialization;
    attrs[0].val.programmaticStreamSerializationAllowed = 1;
    cfg.attrs = attrs;
    cfg.numAttrs = 1;
    cudaLaunchKernelEx(&cfg, k2_address, gate, shift, sharpen, last, out);
}